// round 12
// baseline (speedup 1.0000x reference)
#include <cuda_runtime.h>
#include <cuda_bf16.h>
#include <cstdint>
#include <cmath>

#define Bn 8192
#define Dn 2048
#define Cn 751
#define CnP 768
#define NCAMS 16
#define MARGINF 0.3f
#define IT (1.0f/0.07f)
#define L2E 1.44269504f
#define LN2f 0.69314718f
#define CEXP (IT*L2E)
#define BIGF 1.0e9f
#define L_TRI 0.5f
#define L_ST 0.3f

#define BM 128
#define BK 64
#define KT 32
#define NBLK (Bn/BM)                    // 64
#define NTILE_PAIR (NBLK*(NBLK+1)/2)    // 2080
#define NFULL 1888                      // full pair tiles
#define NSPLIT_T (NTILE_PAIR-NFULL)     // 192 pair tiles run as halves
#define NTILE_CLS  (NBLK*(CnP/BM))      // 384
#define NHALF (2*NSPLIT_T)              // 384 half tiles
#define NTILE_ALL (NFULL+NTILE_CLS+NHALF)   // 2656
#define STG 32768
#define NST 3
#define SM_REACH (NST*STG)
#define SM_SQ  (SM_REACH+1024)
#define SM_INV (SM_SQ+512)
#define SM_TS  (SM_INV+512)
#define SM_LAB (SM_TS+512)
#define SM_CAM (SM_LAB+512)
#define SM_B   (SM_CAM+512)
#define SMEM_TOTAL (SM_B+512)           // 102400

#define SW2(row, ch) ((row)*128 + ((((ch) ^ ((row)&7)))<<4))

// ---------------- device scratch ----------------
__device__ __nv_bfloat16 g_Fb[(size_t)Bn*Dn];
__device__ __nv_bfloat16 g_Wb[(size_t)CnP*Dn];
__device__ float    g_sq[Bn], g_invn[Bn];
__device__ float    g_sume[Bn], g_spos[Bn], g_cpos[Bn];
__device__ unsigned g_hp[Bn], g_hn[Bn];
__device__ float    g_sume_cls[Bn], g_lab_logit[Bn];
__device__ float    g_acc[8];
__device__ unsigned g_done = 0;

__device__ __forceinline__ unsigned f2o(float f){
    unsigned u = __float_as_uint(f);
    return (u & 0x80000000u) ? ~u : (u | 0x80000000u);
}
__device__ __forceinline__ float o2f(unsigned u){
    return __uint_as_float((u & 0x80000000u) ? (u & 0x7fffffffu) : ~u);
}
__device__ __forceinline__ uint32_t pack_bf(float a, float b){
    __nv_bfloat162 t = __floats2bfloat162_rn(a, b);
    return *reinterpret_cast<uint32_t*>(&t);
}
__device__ __forceinline__ float sq2(uint32_t u){
    __nv_bfloat162 h = *reinterpret_cast<__nv_bfloat162*>(&u);
    float2 f = __bfloat1622float2(h);
    return f.x*f.x + f.y*f.y;
}

#define CP16(dst, src) asm volatile("cp.async.cg.shared.global [%0], [%1], 16;" :: "r"(dst), "l"(src) : "memory")
#define CP_COMMIT()    asm volatile("cp.async.commit_group;" ::: "memory")
#define CP_WAIT(n)     asm volatile("cp.async.wait_group %0;" :: "n"(n) : "memory")

__device__ __forceinline__ void ldm4(uint32_t &r0, uint32_t &r1, uint32_t &r2, uint32_t &r3, uint32_t addr){
    asm volatile("ldmatrix.sync.aligned.m8n8.x4.shared.b16 {%0,%1,%2,%3}, [%4];"
        : "=r"(r0), "=r"(r1), "=r"(r2), "=r"(r3) : "r"(addr));
}
__device__ __forceinline__ void mma16816(float* d, const uint32_t* a, const uint32_t* b){
    asm volatile("mma.sync.aligned.m16n8k16.row.col.f32.bf16.bf16.f32 "
        "{%0,%1,%2,%3}, {%4,%5,%6,%7}, {%8,%9}, {%0,%1,%2,%3};"
        : "+f"(d[0]), "+f"(d[1]), "+f"(d[2]), "+f"(d[3])
        : "r"(a[0]), "r"(a[1]), "r"(a[2]), "r"(a[3]), "r"(b[0]), "r"(b[1]));
}

// ---------------- convert F+W, norms+init fused ----------------
__global__ void convert_kernel(const float* __restrict__ F, const float* __restrict__ W){
    __shared__ float s_part[8];
    int b = blockIdx.x, tid = threadIdx.x;
    if (b < Bn){
        size_t i = ((size_t)b*256 + tid)*8;
        float4 v0 = *(const float4*)(F+i);
        float4 v1 = *(const float4*)(F+i+4);
        uint4 o;
        o.x = pack_bf(v0.x, v0.y); o.y = pack_bf(v0.z, v0.w);
        o.z = pack_bf(v1.x, v1.y); o.w = pack_bf(v1.z, v1.w);
        *(uint4*)(g_Fb + i) = o;
        float s = sq2(o.x)+sq2(o.y)+sq2(o.z)+sq2(o.w);
        #pragma unroll
        for (int of=16;of;of>>=1) s += __shfl_xor_sync(0xffffffffu, s, of);
        if ((tid&31)==0) s_part[tid>>5] = s;
        __syncthreads();
        if (tid==0){
            float t = 0.f;
            #pragma unroll
            for (int w=0;w<8;w++) t += s_part[w];
            g_sq[b]=t; g_invn[b]=rsqrtf(t);
            g_sume[b]=0.f; g_spos[b]=0.f; g_cpos[b]=0.f;
            g_hp[b]=f2o(-BIGF); g_hn[b]=f2o(BIGF);
            g_sume_cls[b]=0.f; g_lab_logit[b]=0.f;
            if (b<8) g_acc[b]=0.f;
        }
    } else {
        size_t i = ((size_t)(b-Bn)*256 + tid)*8;
        size_t row = i / Dn;
        uint4 o;
        if (row < Cn){
            float4 v0 = *(const float4*)(W+i);
            float4 v1 = *(const float4*)(W+i+4);
            o.x = pack_bf(v0.x, v0.y); o.y = pack_bf(v0.z, v0.w);
            o.z = pack_bf(v1.x, v1.y); o.w = pack_bf(v1.z, v1.w);
        } else { o.x=o.y=o.z=o.w=0u; }
        *(uint4*)(g_Wb + i) = o;
    }
}

// triangle decode: t -> (I, J) with I <= J
__device__ __forceinline__ void tri_decode(int t, int &I, int &J){
    I = (int)((129.0 - sqrt(16641.0 - 8.0*(double)t))*0.5);
    if (I < 0) I = 0; if (I > 63) I = 63;
    while (I < 63 && ((I+1)*(129-(I+1)))/2 <= t) I++;
    while (((I)*(129-I))/2 > t) I--;
    J = I + (t - (I*(129-I))/2);
}

// ---------------- mega kernel: 1888 full pair + 384 cls + 384 half pair tiles ----------------
__global__ __launch_bounds__(256,2) void mega_kernel(
    const int* __restrict__ lab, const int* __restrict__ cam,
    const float* __restrict__ ts, const float* __restrict__ reach,
    const float* __restrict__ bbias)
{
    extern __shared__ char smem[];
    uint32_t sb = (uint32_t)__cvta_generic_to_shared(smem);
    int tid = threadIdx.x, lane = tid&31, wid = tid>>5;
    int wm = wid&3, wn = wid>>2;

    int t = blockIdx.x;
    int mode;                    // 0 = full pair, 1 = cls, 2 = half pair
    bool diag = false;
    int row0, col0;
    const __nv_bfloat16* gBbase = g_Fb;
    if (t < NFULL){
        mode = 0;
        int I, J; tri_decode(t, I, J);
        diag = (I == J);
        row0 = I*BM; col0 = J*BM;
    } else if (t < NFULL + NTILE_CLS){
        mode = 1;
        int c = t - NFULL;
        row0 = (c/6)*BM; col0 = (c%6)*BM;
        gBbase = g_Wb;
    } else {
        mode = 2;
        int hid = t - NFULL - NTILE_CLS;
        int I, J; tri_decode(NFULL + (hid>>1), I, J);
        diag = (I == J);
        row0 = I*BM; col0 = J*BM + (hid&1)*64;
    }

    float* s_reach=(float*)(smem+SM_REACH);
    float* s_sq  =(float*)(smem+SM_SQ);
    float* s_invn=(float*)(smem+SM_INV);
    float* s_ts  =(float*)(smem+SM_TS);
    int*   s_lab =(int*)  (smem+SM_LAB);
    int*   s_cam =(int*)  (smem+SM_CAM);
    float* s_b   =(float*)(smem+SM_B);
    if (mode != 1){
        s_reach[tid] = reach[tid];
        int nc = (mode==2) ? 64 : 128;
        if (tid < nc){
            int cj = col0 + tid;
            s_sq[tid]=g_sq[cj]; s_invn[tid]=g_invn[cj]; s_ts[tid]=ts[cj];
            s_lab[tid]=lab[cj]; s_cam[tid]=cam[cj];
        }
    } else if (tid < 128){
        int cj = col0 + tid;
        s_b[tid] = (cj < Cn) ? bbias[cj] : 0.f;
    }

    int rL = tid>>3, cL = tid&7;
    uint32_t dA = SW2(rL, cL);
    const __nv_bfloat16* gA = g_Fb + (size_t)(row0+rL)*Dn + cL*8;
    const __nv_bfloat16* gB = gBbase + (size_t)(col0+rL)*Dn + cL*8;

    int q = lane>>3, rr = lane&7;
    int qhi = q>>1, qlo = q&1;

    if (mode != 2){
        // ================= FULL 128x128 path (identical to proven R9/R11) =================
        bool isCls = (mode == 1);
        int rowA[2], rowB[4];
        #pragma unroll
        for (int mt=0; mt<2; mt++) rowA[mt] = (wm*32 + mt*16 + rr + qlo*8)*128;
        #pragma unroll
        for (int nt4=0; nt4<4; nt4++) rowB[nt4] = 16384 + (wn*64 + nt4*16 + rr + qhi*8)*128;

        float acc[2][8][4];
        #pragma unroll
        for (int i=0;i<2;i++)
            #pragma unroll
            for (int j=0;j<8;j++)
                #pragma unroll
                for (int e=0;e<4;e++) acc[i][j][e]=0.f;

        #define PLOADF(j, stq) do { \
            uint32_t _st = sb + (stq)*STG; \
            size_t _ko = (size_t)(j)*BK; \
            _Pragma("unroll") \
            for (int _i=0;_i<4;_i++){ \
                CP16(_st+dA+4096*_i,       gA + (size_t)(32*_i)*Dn + _ko); \
                CP16(_st+16384+dA+4096*_i, gB + (size_t)(32*_i)*Dn + _ko); \
            } \
        } while(0)

        PLOADF(0,0); CP_COMMIT();
        PLOADF(1,1); CP_COMMIT();

        int cs = 0, ls = 2;
        for (int j=0; j<KT; j++){
            CP_WAIT(1);
            __syncthreads();
            if (j+2 < KT){
                PLOADF(j+2, ls);
                ls++; if (ls==NST) ls=0;
            }
            CP_COMMIT();
            uint32_t st = sb + cs*STG;
            cs++; if (cs==NST) cs=0;
            #pragma unroll
            for (int ks=0; ks<4; ks++){
                uint32_t chA = st + ((((ks*2+qhi) ^ rr))<<4);
                uint32_t chB = st + ((((ks*2+qlo) ^ rr))<<4);
                uint32_t a[2][4], b[8][2];
                ldm4(a[0][0],a[0][1],a[0][2],a[0][3], chA + rowA[0]);
                ldm4(a[1][0],a[1][1],a[1][2],a[1][3], chA + rowA[1]);
                #pragma unroll
                for (int nt4=0; nt4<4; nt4++)
                    ldm4(b[nt4*2][0],b[nt4*2][1],b[nt4*2+1][0],b[nt4*2+1][1], chB + rowB[nt4]);
                #pragma unroll
                for (int mt=0; mt<2; mt++)
                    #pragma unroll
                    for (int nt=0; nt<8; nt++)
                        mma16816(acc[mt][nt], a[mt], b[nt]);
            }
        }
        #undef PLOADF

        if (isCls){
            float se4[4]; int r4c[4], labc[4];
            #pragma unroll
            for (int x=0;x<4;x++){
                int ri = row0 + wm*32 + (x>>1)*16 + (x&1)*8 + (lane>>2);
                r4c[x]=ri; labc[x]=lab[ri]; se4[x]=0.f;
            }
            #pragma unroll
            for (int nt=0; nt<8; nt++)
                #pragma unroll
                for (int u=0; u<2; u++){
                    int cl = wn*64 + nt*8 + (lane&3)*2 + u;
                    int cj = col0 + cl;
                    if (cj < Cn){
                        float bj = s_b[cl];
                        #pragma unroll
                        for (int x=0;x<4;x++){
                            float logit = acc[x>>1][nt][(x&1)*2+u] + bj;
                            se4[x] += __expf(logit);
                            if (cj == labc[x]) g_lab_logit[r4c[x]] = logit;
                        }
                    }
                }
            #pragma unroll
            for (int o=1;o<=2;o<<=1)
                #pragma unroll
                for (int x=0;x<4;x++)
                    se4[x] += __shfl_xor_sync(0xffffffffu, se4[x], o);
            if ((lane&3)==0){
                #pragma unroll
                for (int x=0;x<4;x++) atomicAdd(&g_sume_cls[r4c[x]], se4[x]);
            }
            return;
        }

        // dual-side pair epilogue
        int   r4[4], labi[4], cami[4];
        float sqi[4], ari[4], tsi[4];
        #pragma unroll
        for (int x=0;x<4;x++){
            int ri = row0 + wm*32 + (x>>1)*16 + (x&1)*8 + (lane>>2);
            r4[x]=ri; sqi[x]=g_sq[ri]; ari[x]=g_invn[ri]*CEXP;
            tsi[x]=ts[ri]; labi[x]=lab[ri]; cami[x]=cam[ri];
        }
        float sume4[4], spos4[4], cpos4[4], hp4[4], hn4[4];
        #pragma unroll
        for (int x=0;x<4;x++){ sume4[x]=0.f; spos4[x]=0.f; cpos4[x]=0.f; hp4[x]=-BIGF; hn4[x]=BIGF; }

        #pragma unroll
        for (int nt=0; nt<8; nt++){
            #pragma unroll
            for (int u=0; u<2; u++){
                int cl = wn*64 + nt*8 + (lane&3)*2 + u;
                int cj = col0 + cl;
                float sqj=s_sq[cl], invj=s_invn[cl], tsj=s_ts[cl];
                int labj=s_lab[cl], camj=s_cam[cl];
                float hpC=-BIGF, hnC=BIGF, sumeC=0.f, sposC=0.f, cposC=0.f;
                #pragma unroll
                for (int mt=0; mt<2; mt++){
                    #pragma unroll
                    for (int h=0; h<2; h++){
                        int x = mt*2 + h;
                        float g  = acc[mt][nt][h*2+u];
                        float d2 = fmaxf(fmaf(-2.f, g, sqi[x] + sqj), 0.f);
                        bool eye  = (r4[x] == cj);
                        bool sne  = (labi[x] == labj) && !eye;
                        float tt = fmaf(g*ari[x], invj, -CEXP);
                        float ev; asm("ex2.approx.ftz.f32 %0, %1;" : "=f"(ev) : "f"(tt));
                        float dt = fabsf(tsi[x] - tsj);
                        if (sne) hp4[x] = fmaxf(hp4[x], d2);
                        else     hn4[x] = fminf(hn4[x], d2);
                        sume4[x] += ev;
                        if (sne && dt <= s_reach[cami[x]*NCAMS + camj]){
                            spos4[x] += fmaf(tt, LN2f, IT); cpos4[x] += 1.f;
                        }
                        if (!diag){
                            if (sne) hpC = fmaxf(hpC, d2);
                            else     hnC = fminf(hnC, d2);
                            sumeC += ev;
                            if (sne && dt <= s_reach[camj*NCAMS + cami[x]]){
                                sposC += fmaf(tt, LN2f, IT); cposC += 1.f;
                            }
                        }
                    }
                }
                if (!diag){
                    #pragma unroll
                    for (int o=4; o<=16; o<<=1){
                        sumeC += __shfl_xor_sync(0xffffffffu, sumeC, o);
                        sposC += __shfl_xor_sync(0xffffffffu, sposC, o);
                        cposC += __shfl_xor_sync(0xffffffffu, cposC, o);
                        hpC = fmaxf(hpC, __shfl_xor_sync(0xffffffffu, hpC, o));
                        hnC = fminf(hnC, __shfl_xor_sync(0xffffffffu, hnC, o));
                    }
                    if ((lane>>2) == 0){
                        atomicAdd(&g_sume[cj], sumeC);
                        if (cposC > 0.f){ atomicAdd(&g_spos[cj], sposC); atomicAdd(&g_cpos[cj], cposC); }
                        if (hpC > -BIGF) atomicMax(&g_hp[cj], f2o(hpC));
                        atomicMin(&g_hn[cj], f2o(hnC));
                    }
                }
            }
        }

        #pragma unroll
        for (int o=1; o<=2; o<<=1){
            #pragma unroll
            for (int x=0;x<4;x++){
                sume4[x] += __shfl_xor_sync(0xffffffffu, sume4[x], o);
                spos4[x] += __shfl_xor_sync(0xffffffffu, spos4[x], o);
                cpos4[x] += __shfl_xor_sync(0xffffffffu, cpos4[x], o);
                hp4[x] = fmaxf(hp4[x], __shfl_xor_sync(0xffffffffu, hp4[x], o));
                hn4[x] = fminf(hn4[x], __shfl_xor_sync(0xffffffffu, hn4[x], o));
            }
        }
        if ((lane&3)==0){
            #pragma unroll
            for (int x=0;x<4;x++){
                int ri = r4[x];
                atomicAdd(&g_sume[ri], sume4[x]);
                if (cpos4[x] > 0.f){ atomicAdd(&g_spos[ri], spos4[x]); atomicAdd(&g_cpos[ri], cpos4[x]); }
                if (hp4[x] > -BIGF) atomicMax(&g_hp[ri], f2o(hp4[x]));
                atomicMin(&g_hn[ri], f2o(hn4[x]));
            }
        }
        return;
    }

    // ================= HALF 128x64 path (tail tiles; warp tile 16x64) =================
    {
        int rowA0 = (wid*16 + rr + qlo*8)*128;
        int rowBh[4];
        #pragma unroll
        for (int nt4=0; nt4<4; nt4++) rowBh[nt4] = 16384 + (nt4*16 + rr + qhi*8)*128;

        float acch[8][4];
        #pragma unroll
        for (int j=0;j<8;j++)
            #pragma unroll
            for (int e=0;e<4;e++) acch[j][e]=0.f;

        #define PLOADH(j, stq) do { \
            uint32_t _st = sb + (stq)*STG; \
            size_t _ko = (size_t)(j)*BK; \
            _Pragma("unroll") \
            for (int _i=0;_i<4;_i++) CP16(_st+dA+4096*_i, gA + (size_t)(32*_i)*Dn + _ko); \
            _Pragma("unroll") \
            for (int _i=0;_i<2;_i++) CP16(_st+16384+dA+4096*_i, gB + (size_t)(32*_i)*Dn + _ko); \
        } while(0)

        PLOADH(0,0); CP_COMMIT();
        PLOADH(1,1); CP_COMMIT();

        int cs = 0, ls = 2;
        for (int j=0; j<KT; j++){
            CP_WAIT(1);
            __syncthreads();
            if (j+2 < KT){
                PLOADH(j+2, ls);
                ls++; if (ls==NST) ls=0;
            }
            CP_COMMIT();
            uint32_t st = sb + cs*STG;
            cs++; if (cs==NST) cs=0;
            #pragma unroll
            for (int ks=0; ks<4; ks++){
                uint32_t chA = st + ((((ks*2+qhi) ^ rr))<<4);
                uint32_t chB = st + ((((ks*2+qlo) ^ rr))<<4);
                uint32_t a[4], b[8][2];
                ldm4(a[0],a[1],a[2],a[3], chA + rowA0);
                #pragma unroll
                for (int nt4=0; nt4<4; nt4++)
                    ldm4(b[nt4*2][0],b[nt4*2][1],b[nt4*2+1][0],b[nt4*2+1][1], chB + rowBh[nt4]);
                #pragma unroll
                for (int nt=0; nt<8; nt++)
                    mma16816(acch[nt], a, b[nt]);
            }
        }
        #undef PLOADH

        // dual-side epilogue over 2 rows/thread, 64 cols
        int   r2[2], labi2[2], cami2[2];
        float sqi2[2], ari2[2], tsi2[2];
        #pragma unroll
        for (int x=0;x<2;x++){
            int ri = row0 + wid*16 + x*8 + (lane>>2);
            r2[x]=ri; sqi2[x]=g_sq[ri]; ari2[x]=g_invn[ri]*CEXP;
            tsi2[x]=ts[ri]; labi2[x]=lab[ri]; cami2[x]=cam[ri];
        }
        float sume2[2], spos2[2], cpos2[2], hp2[2], hn2[2];
        #pragma unroll
        for (int x=0;x<2;x++){ sume2[x]=0.f; spos2[x]=0.f; cpos2[x]=0.f; hp2[x]=-BIGF; hn2[x]=BIGF; }

        #pragma unroll
        for (int nt=0; nt<8; nt++){
            #pragma unroll
            for (int u=0; u<2; u++){
                int cl = nt*8 + (lane&3)*2 + u;
                int cj = col0 + cl;
                float sqj=s_sq[cl], invj=s_invn[cl], tsj=s_ts[cl];
                int labj=s_lab[cl], camj=s_cam[cl];
                float hpC=-BIGF, hnC=BIGF, sumeC=0.f, sposC=0.f, cposC=0.f;
                #pragma unroll
                for (int x=0;x<2;x++){
                    float g  = acch[nt][x*2+u];
                    float d2 = fmaxf(fmaf(-2.f, g, sqi2[x] + sqj), 0.f);
                    bool eye  = (r2[x] == cj);
                    bool sne  = (labi2[x] == labj) && !eye;
                    float tt = fmaf(g*ari2[x], invj, -CEXP);
                    float ev; asm("ex2.approx.ftz.f32 %0, %1;" : "=f"(ev) : "f"(tt));
                    float dt = fabsf(tsi2[x] - tsj);
                    if (sne) hp2[x] = fmaxf(hp2[x], d2);
                    else     hn2[x] = fminf(hn2[x], d2);
                    sume2[x] += ev;
                    if (sne && dt <= s_reach[cami2[x]*NCAMS + camj]){
                        spos2[x] += fmaf(tt, LN2f, IT); cpos2[x] += 1.f;
                    }
                    if (!diag){
                        if (sne) hpC = fmaxf(hpC, d2);
                        else     hnC = fminf(hnC, d2);
                        sumeC += ev;
                        if (sne && dt <= s_reach[camj*NCAMS + cami2[x]]){
                            sposC += fmaf(tt, LN2f, IT); cposC += 1.f;
                        }
                    }
                }
                if (!diag){
                    #pragma unroll
                    for (int o=4; o<=16; o<<=1){
                        sumeC += __shfl_xor_sync(0xffffffffu, sumeC, o);
                        sposC += __shfl_xor_sync(0xffffffffu, sposC, o);
                        cposC += __shfl_xor_sync(0xffffffffu, cposC, o);
                        hpC = fmaxf(hpC, __shfl_xor_sync(0xffffffffu, hpC, o));
                        hnC = fminf(hnC, __shfl_xor_sync(0xffffffffu, hnC, o));
                    }
                    if ((lane>>2) == 0){
                        atomicAdd(&g_sume[cj], sumeC);
                        if (cposC > 0.f){ atomicAdd(&g_spos[cj], sposC); atomicAdd(&g_cpos[cj], cposC); }
                        if (hpC > -BIGF) atomicMax(&g_hp[cj], f2o(hpC));
                        atomicMin(&g_hn[cj], f2o(hnC));
                    }
                }
            }
        }

        #pragma unroll
        for (int o=1; o<=2; o<<=1){
            #pragma unroll
            for (int x=0;x<2;x++){
                sume2[x] += __shfl_xor_sync(0xffffffffu, sume2[x], o);
                spos2[x] += __shfl_xor_sync(0xffffffffu, spos2[x], o);
                cpos2[x] += __shfl_xor_sync(0xffffffffu, cpos2[x], o);
                hp2[x] = fmaxf(hp2[x], __shfl_xor_sync(0xffffffffu, hp2[x], o));
                hn2[x] = fminf(hn2[x], __shfl_xor_sync(0xffffffffu, hn2[x], o));
            }
        }
        if ((lane&3)==0){
            #pragma unroll
            for (int x=0;x<2;x++){
                int ri = r2[x];
                atomicAdd(&g_sume[ri], sume2[x]);
                if (cpos2[x] > 0.f){ atomicAdd(&g_spos[ri], spos2[x]); atomicAdd(&g_cpos[ri], cpos2[x]); }
                if (hp2[x] > -BIGF) atomicMax(&g_hp[ri], f2o(hp2[x]));
                atomicMin(&g_hn[ri], f2o(hn2[x]));
            }
        }
    }
}

// ---------------- finalization (single kernel, last-block pattern) ----------------
__global__ void fin1(float* out){
    int i = blockIdx.x*blockDim.x + threadIdx.x;
    float tri=0.f, nv=0.f, stn=0.f, stc=0.f, cls=0.f;
    if (i < Bn){
        float lse = IT + logf(g_sume[i]);
        stn = g_spos[i] - g_cpos[i]*lse;
        stc = g_cpos[i];
        float hp = o2f(g_hp[i]), hn = o2f(g_hn[i]);
        bool valid = hp > -1.0e8f;
        tri = valid ? fmaxf(hp - hn + MARGINF, 0.f) : 0.f;
        nv  = valid ? 1.f : 0.f;
        cls = logf(g_sume_cls[i]) - g_lab_logit[i];
    }
    #pragma unroll
    for (int o=16;o;o>>=1){
        tri += __shfl_down_sync(0xffffffffu, tri, o);
        nv  += __shfl_down_sync(0xffffffffu, nv , o);
        stn += __shfl_down_sync(0xffffffffu, stn, o);
        stc += __shfl_down_sync(0xffffffffu, stc, o);
        cls += __shfl_down_sync(0xffffffffu, cls, o);
    }
    if ((threadIdx.x & 31) == 0){
        atomicAdd(&g_acc[0], tri);
        atomicAdd(&g_acc[1], nv);
        atomicAdd(&g_acc[2], stn);
        atomicAdd(&g_acc[3], stc);
        atomicAdd(&g_acc[4], cls);
    }
    __syncthreads();
    __threadfence();
    if (threadIdx.x == 0){
        unsigned prev = atomicAdd(&g_done, 1u);
        if (prev == (unsigned)(gridDim.x - 1)){
            float nvv = g_acc[1], npos = g_acc[3];
            float loss_id  = g_acc[4] / (float)Bn;
            float loss_tri = (nvv  > 0.f) ? g_acc[0] / fmaxf(nvv,  1.f) : 0.f;
            float loss_st  = (npos > 0.f) ? (-g_acc[2]) / fmaxf(npos, 1.f) : 0.f;
            out[0] = loss_id + L_TRI*loss_tri + L_ST*loss_st;
            g_done = 0;   // reset for graph replay
        }
    }
}

// ---------------- launch ----------------
extern "C" void kernel_launch(void* const* d_in, const int* in_sizes, int n_in,
                              void* d_out, int out_size){
    const float* F     = (const float*)d_in[0];
    const int*   lab   = (const int*)  d_in[1];
    const int*   cam   = (const int*)  d_in[2];
    const float* ts    = (const float*)d_in[3];
    const float* reach = (const float*)d_in[4];
    const float* W     = (const float*)d_in[5];
    const float* bbias = (const float*)d_in[6];
    float* out = (float*)d_out;

    cudaFuncSetAttribute(mega_kernel, cudaFuncAttributeMaxDynamicSharedMemorySize, SMEM_TOTAL);

    convert_kernel<<<Bn + CnP, 256>>>(F, W);
    mega_kernel<<<NTILE_ALL, 256, SMEM_TOTAL>>>(lab, cam, ts, reach, bbias);
    fin1<<<Bn/256, 256>>>(out);
}

// round 13
// speedup vs baseline: 1.0925x; 1.0925x over previous
#include <cuda_runtime.h>
#include <cuda_bf16.h>
#include <cstdint>
#include <cmath>

#define Bn 8192
#define Dn 2048
#define Cn 751
#define CnP 768
#define NCAMS 16
#define MARGINF 0.3f
#define IT (1.0f/0.07f)
#define L2E 1.44269504f
#define LN2f 0.69314718f
#define CEXP (IT*L2E)
#define BIGF 1.0e9f
#define L_TRI 0.5f
#define L_ST 0.3f

#define BM 128
#define BK 64
#define KT 32
#define NBLK (Bn/BM)                    // 64
#define NTILE_PAIR (NBLK*(NBLK+1)/2)    // 2080
#define NTILE_CLS  (NBLK*(CnP/BM))      // 384
#define NTILE_ALL  (NTILE_PAIR+NTILE_CLS)
#define STG 32768
#define NST 3
#define SM_REACH (NST*STG)
#define SM_SQ  (SM_REACH+1024)
#define SM_INV (SM_SQ+512)
#define SM_TS  (SM_INV+512)
#define SM_LAB (SM_TS+512)
#define SM_CAM (SM_LAB+512)
#define SM_B   (SM_CAM+512)
#define SMEM_TOTAL (SM_B+512)           // 102400

#define SW2(row, ch) ((row)*128 + ((((ch) ^ ((row)&7)))<<4))

// ---------------- device scratch ----------------
__device__ __nv_bfloat16 g_Fb[(size_t)Bn*Dn];
__device__ __nv_bfloat16 g_Wb[(size_t)CnP*Dn];
__device__ float    g_sq[Bn], g_invn[Bn];
__device__ float    g_sume[Bn], g_spos[Bn], g_cpos[Bn];
__device__ unsigned g_hp[Bn];
__device__ float    g_sume_cls[Bn], g_lab_logit[Bn];
__device__ float    g_acc[8];
__device__ unsigned g_done = 0;

__device__ __forceinline__ unsigned f2o(float f){
    unsigned u = __float_as_uint(f);
    return (u & 0x80000000u) ? ~u : (u | 0x80000000u);
}
__device__ __forceinline__ float o2f(unsigned u){
    return __uint_as_float((u & 0x80000000u) ? (u & 0x7fffffffu) : ~u);
}
__device__ __forceinline__ uint32_t pack_bf(float a, float b){
    __nv_bfloat162 t = __floats2bfloat162_rn(a, b);
    return *reinterpret_cast<uint32_t*>(&t);
}
__device__ __forceinline__ float sq2(uint32_t u){
    __nv_bfloat162 h = *reinterpret_cast<__nv_bfloat162*>(&u);
    float2 f = __bfloat1622float2(h);
    return f.x*f.x + f.y*f.y;
}

#define CP16(dst, src) asm volatile("cp.async.cg.shared.global [%0], [%1], 16;" :: "r"(dst), "l"(src) : "memory")
#define CP_COMMIT()    asm volatile("cp.async.commit_group;" ::: "memory")
#define CP_WAIT(n)     asm volatile("cp.async.wait_group %0;" :: "n"(n) : "memory")

__device__ __forceinline__ void ldm4(uint32_t &r0, uint32_t &r1, uint32_t &r2, uint32_t &r3, uint32_t addr){
    asm volatile("ldmatrix.sync.aligned.m8n8.x4.shared.b16 {%0,%1,%2,%3}, [%4];"
        : "=r"(r0), "=r"(r1), "=r"(r2), "=r"(r3) : "r"(addr));
}
__device__ __forceinline__ void mma16816(float* d, const uint32_t* a, const uint32_t* b){
    asm volatile("mma.sync.aligned.m16n8k16.row.col.f32.bf16.bf16.f32 "
        "{%0,%1,%2,%3}, {%4,%5,%6,%7}, {%8,%9}, {%0,%1,%2,%3};"
        : "+f"(d[0]), "+f"(d[1]), "+f"(d[2]), "+f"(d[3])
        : "r"(a[0]), "r"(a[1]), "r"(a[2]), "r"(a[3]), "r"(b[0]), "r"(b[1]));
}

// ---------------- convert F+W, norms+init fused (block b == row b for F) ----------------
__global__ void convert_kernel(const float* __restrict__ F, const float* __restrict__ W){
    __shared__ float s_part[8];
    int b = blockIdx.x, tid = threadIdx.x;
    if (b < Bn){
        size_t i = ((size_t)b*256 + tid)*8;
        float4 v0 = *(const float4*)(F+i);
        float4 v1 = *(const float4*)(F+i+4);
        uint4 o;
        o.x = pack_bf(v0.x, v0.y); o.y = pack_bf(v0.z, v0.w);
        o.z = pack_bf(v1.x, v1.y); o.w = pack_bf(v1.z, v1.w);
        *(uint4*)(g_Fb + i) = o;
        float s = sq2(o.x)+sq2(o.y)+sq2(o.z)+sq2(o.w);
        #pragma unroll
        for (int of=16;of;of>>=1) s += __shfl_xor_sync(0xffffffffu, s, of);
        if ((tid&31)==0) s_part[tid>>5] = s;
        __syncthreads();
        if (tid==0){
            float t = 0.f;
            #pragma unroll
            for (int w=0;w<8;w++) t += s_part[w];
            g_sq[b]=t; g_invn[b]=rsqrtf(t);
            g_sume[b]=0.f; g_spos[b]=0.f; g_cpos[b]=0.f;
            g_hp[b]=f2o(-BIGF);
            g_sume_cls[b]=0.f; g_lab_logit[b]=0.f;
            if (b<8) g_acc[b]=0.f;
        }
    } else {
        size_t i = ((size_t)(b-Bn)*256 + tid)*8;
        size_t row = i / Dn;
        uint4 o;
        if (row < Cn){
            float4 v0 = *(const float4*)(W+i);
            float4 v1 = *(const float4*)(W+i+4);
            o.x = pack_bf(v0.x, v0.y); o.y = pack_bf(v0.z, v0.w);
            o.z = pack_bf(v1.x, v1.y); o.w = pack_bf(v1.z, v1.w);
        } else { o.x=o.y=o.z=o.w=0u; }
        *(uint4*)(g_Wb + i) = o;
    }
}

// ---------------- mega kernel: 2080 pair tiles + 384 cls tiles, 128x128, 2 CTA/SM ----------------
__global__ __launch_bounds__(256,2) void mega_kernel(
    const int* __restrict__ lab, const int* __restrict__ cam,
    const float* __restrict__ ts, const float* __restrict__ reach,
    const float* __restrict__ bbias)
{
    extern __shared__ char smem[];
    uint32_t sb = (uint32_t)__cvta_generic_to_shared(smem);
    int tid = threadIdx.x, lane = tid&31, wid = tid>>5;
    int wm = wid&3, wn = wid>>2;

    int t = blockIdx.x;
    bool isCls = (t >= NTILE_PAIR);
    bool diag = false;
    int row0, col0;
    const __nv_bfloat16* gBbase;
    if (isCls){
        int c = t - NTILE_PAIR;
        row0 = (c/6)*BM; col0 = (c%6)*BM;
        gBbase = g_Wb;
    } else {
        int I = (int)((129.0 - sqrt(16641.0 - 8.0*(double)t))*0.5);
        if (I < 0) I = 0; if (I > 63) I = 63;
        while (I < 63 && ((I+1)*(129-(I+1)))/2 <= t) I++;
        while (((I)*(129-I))/2 > t) I--;
        int J = I + (t - (I*(129-I))/2);
        diag = (I == J);
        row0 = I*BM; col0 = J*BM;
        gBbase = g_Fb;
    }

    float* s_reach=(float*)(smem+SM_REACH);
    float* s_sq  =(float*)(smem+SM_SQ);
    float* s_invn=(float*)(smem+SM_INV);
    float* s_ts  =(float*)(smem+SM_TS);
    int*   s_lab =(int*)  (smem+SM_LAB);
    int*   s_cam =(int*)  (smem+SM_CAM);
    float* s_b   =(float*)(smem+SM_B);
    if (!isCls){
        s_reach[tid] = reach[tid];
        if (tid < 128){
            int cj = col0 + tid;
            s_sq[tid]=g_sq[cj]; s_invn[tid]=g_invn[cj]; s_ts[tid]=ts[cj];
            s_lab[tid]=lab[cj]; s_cam[tid]=cam[cj];
        }
    } else if (tid < 128){
        int cj = col0 + tid;
        s_b[tid] = (cj < Cn) ? bbias[cj] : 0.f;
    }

    // loaders: 4 chunks of A + 4 of B per thread per stage
    int rL = tid>>3, cL = tid&7;
    uint32_t dA = SW2(rL, cL);
    const __nv_bfloat16* gA = g_Fb + (size_t)(row0+rL)*Dn + cL*8;
    const __nv_bfloat16* gB = gBbase + (size_t)(col0+rL)*Dn + cL*8;

    int q = lane>>3, rr = lane&7;
    int rowA[2], rowB[4];
    #pragma unroll
    for (int mt=0; mt<2; mt++) rowA[mt] = (wm*32 + mt*16 + rr + (q&1)*8)*128;
    #pragma unroll
    for (int nt4=0; nt4<4; nt4++) rowB[nt4] = 16384 + (wn*64 + nt4*16 + rr + (q>>1)*8)*128;
    int qhi = q>>1, qlo = q&1;

    float acc[2][8][4];
    #pragma unroll
    for (int i=0;i<2;i++)
        #pragma unroll
        for (int j=0;j<8;j++)
            #pragma unroll
            for (int e=0;e<4;e++) acc[i][j][e]=0.f;

    #define PLOAD(j, stq) do { \
        uint32_t _st = sb + (stq)*STG; \
        size_t _ko = (size_t)(j)*BK; \
        _Pragma("unroll") \
        for (int _i=0;_i<4;_i++){ \
            CP16(_st+dA+4096*_i,       gA + (size_t)(32*_i)*Dn + _ko); \
            CP16(_st+16384+dA+4096*_i, gB + (size_t)(32*_i)*Dn + _ko); \
        } \
    } while(0)

    PLOAD(0,0); CP_COMMIT();
    PLOAD(1,1); CP_COMMIT();

    int cs = 0, ls = 2;
    for (int j=0; j<KT; j++){
        CP_WAIT(1);
        __syncthreads();
        if (j+2 < KT){
            PLOAD(j+2, ls);
            ls++; if (ls==NST) ls=0;
        }
        CP_COMMIT();
        uint32_t st = sb + cs*STG;
        cs++; if (cs==NST) cs=0;
        #pragma unroll
        for (int ks=0; ks<4; ks++){
            uint32_t chA = st + ((((ks*2+qhi) ^ rr))<<4);
            uint32_t chB = st + ((((ks*2+qlo) ^ rr))<<4);
            uint32_t a[2][4], b[8][2];
            ldm4(a[0][0],a[0][1],a[0][2],a[0][3], chA + rowA[0]);
            ldm4(a[1][0],a[1][1],a[1][2],a[1][3], chA + rowA[1]);
            #pragma unroll
            for (int nt4=0; nt4<4; nt4++)
                ldm4(b[nt4*2][0],b[nt4*2][1],b[nt4*2+1][0],b[nt4*2+1][1], chB + rowB[nt4]);
            #pragma unroll
            for (int mt=0; mt<2; mt++)
                #pragma unroll
                for (int nt=0; nt<8; nt++)
                    mma16816(acc[mt][nt], a[mt], b[nt]);
        }
    }
    #undef PLOAD

    if (isCls){
        // ---- classifier epilogue ----
        float se4[4]; int r4c[4], labc[4];
        #pragma unroll
        for (int x=0;x<4;x++){
            int ri = row0 + wm*32 + (x>>1)*16 + (x&1)*8 + (lane>>2);
            r4c[x]=ri; labc[x]=lab[ri]; se4[x]=0.f;
        }
        #pragma unroll
        for (int nt=0; nt<8; nt++)
            #pragma unroll
            for (int u=0; u<2; u++){
                int cl = wn*64 + nt*8 + (lane&3)*2 + u;
                int cj = col0 + cl;
                if (cj < Cn){
                    float bj = s_b[cl];
                    #pragma unroll
                    for (int x=0;x<4;x++){
                        float logit = acc[x>>1][nt][(x&1)*2+u] + bj;
                        se4[x] += __expf(logit);
                        if (cj == labc[x]) g_lab_logit[r4c[x]] = logit;
                    }
                }
            }
        #pragma unroll
        for (int o=1;o<=2;o<<=1)
            #pragma unroll
            for (int x=0;x<4;x++)
                se4[x] += __shfl_xor_sync(0xffffffffu, se4[x], o);
        if ((lane&3)==0){
            #pragma unroll
            for (int x=0;x<4;x++) atomicAdd(&g_sume_cls[r4c[x]], se4[x]);
        }
        return;
    }

    // ---- dual-side pair epilogue (hardest_neg == 0 identically; not tracked) ----
    int   r4[4], labi[4], cami[4];
    float sqi[4], ari[4], tsi[4];
    #pragma unroll
    for (int x=0;x<4;x++){
        int ri = row0 + wm*32 + (x>>1)*16 + (x&1)*8 + (lane>>2);
        r4[x]=ri; sqi[x]=g_sq[ri]; ari[x]=g_invn[ri]*CEXP;
        tsi[x]=ts[ri]; labi[x]=lab[ri]; cami[x]=cam[ri];
    }
    float sume4[4], spos4[4], cpos4[4], hp4[4];
    #pragma unroll
    for (int x=0;x<4;x++){ sume4[x]=0.f; spos4[x]=0.f; cpos4[x]=0.f; hp4[x]=-BIGF; }

    #pragma unroll
    for (int nt=0; nt<8; nt++){
        #pragma unroll
        for (int u=0; u<2; u++){
            int cl = wn*64 + nt*8 + (lane&3)*2 + u;
            int cj = col0 + cl;
            float sqj=s_sq[cl], invj=s_invn[cl], tsj=s_ts[cl];
            int labj=s_lab[cl], camj=s_cam[cl];
            float hpC=-BIGF, sumeC=0.f, sposC=0.f, cposC=0.f;
            #pragma unroll
            for (int mt=0; mt<2; mt++){
                #pragma unroll
                for (int h=0; h<2; h++){
                    int x = mt*2 + h;
                    float g  = acc[mt][nt][h*2+u];
                    bool eye  = (r4[x] == cj);
                    bool sne  = (labi[x] == labj) && !eye;
                    float tt = fmaf(g*ari[x], invj, -CEXP);
                    float ev; asm("ex2.approx.ftz.f32 %0, %1;" : "=f"(ev) : "f"(tt));
                    float dt = fabsf(tsi[x] - tsj);
                    sume4[x] += ev;
                    if (sne){
                        float d2 = fmaxf(fmaf(-2.f, g, sqi[x] + sqj), 0.f);
                        hp4[x] = fmaxf(hp4[x], d2);
                        if (dt <= s_reach[cami[x]*NCAMS + camj]){
                            spos4[x] += fmaf(tt, LN2f, IT); cpos4[x] += 1.f;
                        }
                        if (!diag){
                            hpC = fmaxf(hpC, d2);
                            if (dt <= s_reach[camj*NCAMS + cami[x]]){
                                sposC += fmaf(tt, LN2f, IT); cposC += 1.f;
                            }
                        }
                    }
                    if (!diag) sumeC += ev;
                }
            }
            if (!diag){
                #pragma unroll
                for (int o=4; o<=16; o<<=1){
                    sumeC += __shfl_xor_sync(0xffffffffu, sumeC, o);
                    sposC += __shfl_xor_sync(0xffffffffu, sposC, o);
                    cposC += __shfl_xor_sync(0xffffffffu, cposC, o);
                    hpC = fmaxf(hpC, __shfl_xor_sync(0xffffffffu, hpC, o));
                }
                if ((lane>>2) == 0){
                    atomicAdd(&g_sume[cj], sumeC);
                    if (cposC > 0.f){ atomicAdd(&g_spos[cj], sposC); atomicAdd(&g_cpos[cj], cposC); }
                    if (hpC > -BIGF) atomicMax(&g_hp[cj], f2o(hpC));
                }
            }
        }
    }

    // row-side merge
    #pragma unroll
    for (int o=1; o<=2; o<<=1){
        #pragma unroll
        for (int x=0;x<4;x++){
            sume4[x] += __shfl_xor_sync(0xffffffffu, sume4[x], o);
            spos4[x] += __shfl_xor_sync(0xffffffffu, spos4[x], o);
            cpos4[x] += __shfl_xor_sync(0xffffffffu, cpos4[x], o);
            hp4[x] = fmaxf(hp4[x], __shfl_xor_sync(0xffffffffu, hp4[x], o));
        }
    }
    if ((lane&3)==0){
        #pragma unroll
        for (int x=0;x<4;x++){
            int ri = r4[x];
            atomicAdd(&g_sume[ri], sume4[x]);
            if (cpos4[x] > 0.f){ atomicAdd(&g_spos[ri], spos4[x]); atomicAdd(&g_cpos[ri], cpos4[x]); }
            if (hp4[x] > -BIGF) atomicMax(&g_hp[ri], f2o(hp4[x]));
        }
    }
}

// ---------------- finalization (single kernel, last-block pattern) ----------------
__global__ void fin1(float* out){
    int i = blockIdx.x*blockDim.x + threadIdx.x;
    float tri=0.f, nv=0.f, stn=0.f, stc=0.f, cls=0.f;
    if (i < Bn){
        float lse = IT + logf(g_sume[i]);
        stn = g_spos[i] - g_cpos[i]*lse;
        stc = g_cpos[i];
        float hp = o2f(g_hp[i]);
        bool valid = hp > -1.0e8f;
        tri = valid ? fmaxf(hp + MARGINF, 0.f) : 0.f;   // hardest_neg == 0 identically
        nv  = valid ? 1.f : 0.f;
        cls = logf(g_sume_cls[i]) - g_lab_logit[i];
    }
    #pragma unroll
    for (int o=16;o;o>>=1){
        tri += __shfl_down_sync(0xffffffffu, tri, o);
        nv  += __shfl_down_sync(0xffffffffu, nv , o);
        stn += __shfl_down_sync(0xffffffffu, stn, o);
        stc += __shfl_down_sync(0xffffffffu, stc, o);
        cls += __shfl_down_sync(0xffffffffu, cls, o);
    }
    if ((threadIdx.x & 31) == 0){
        atomicAdd(&g_acc[0], tri);
        atomicAdd(&g_acc[1], nv);
        atomicAdd(&g_acc[2], stn);
        atomicAdd(&g_acc[3], stc);
        atomicAdd(&g_acc[4], cls);
    }
    __syncthreads();
    __threadfence();
    if (threadIdx.x == 0){
        unsigned prev = atomicAdd(&g_done, 1u);
        if (prev == (unsigned)(gridDim.x - 1)){
            float nvv = g_acc[1], npos = g_acc[3];
            float loss_id  = g_acc[4] / (float)Bn;
            float loss_tri = (nvv  > 0.f) ? g_acc[0] / fmaxf(nvv,  1.f) : 0.f;
            float loss_st  = (npos > 0.f) ? (-g_acc[2]) / fmaxf(npos, 1.f) : 0.f;
            out[0] = loss_id + L_TRI*loss_tri + L_ST*loss_st;
            g_done = 0;   // reset for graph replay
        }
    }
}

// ---------------- launch ----------------
extern "C" void kernel_launch(void* const* d_in, const int* in_sizes, int n_in,
                              void* d_out, int out_size){
    const float* F     = (const float*)d_in[0];
    const int*   lab   = (const int*)  d_in[1];
    const int*   cam   = (const int*)  d_in[2];
    const float* ts    = (const float*)d_in[3];
    const float* reach = (const float*)d_in[4];
    const float* W     = (const float*)d_in[5];
    const float* bbias = (const float*)d_in[6];
    float* out = (float*)d_out;

    cudaFuncSetAttribute(mega_kernel, cudaFuncAttributeMaxDynamicSharedMemorySize, SMEM_TOTAL);

    convert_kernel<<<Bn + CnP, 256>>>(F, W);
    mega_kernel<<<NTILE_ALL, 256, SMEM_TOTAL>>>(lab, cam, ts, reach, bbias);
    fin1<<<Bn/256, 256>>>(out);
}

// round 14
// speedup vs baseline: 1.0955x; 1.0028x over previous
#include <cuda_runtime.h>
#include <cuda_bf16.h>
#include <cstdint>
#include <cmath>

#define Bn 8192
#define Dn 2048
#define Cn 751
#define CnP 768
#define NCAMS 16
#define MARGINF 0.3f
#define IT (1.0f/0.07f)
#define L2E 1.44269504f
#define LN2f 0.69314718f
#define CEXP (IT*L2E)
#define BIGF 1.0e9f
#define L_TRI 0.5f
#define L_ST 0.3f

#define BM 128
#define BK 64
#define KT 32
#define NBLK (Bn/BM)                    // 64
#define NTILE_PAIR (NBLK*(NBLK+1)/2)    // 2080
#define NTILE_CLS  (NBLK*(CnP/BM))      // 384
#define NTILE_ALL  (NTILE_PAIR+NTILE_CLS)
#define STG 32768
#define NST 3
#define SM_REACH (NST*STG)
#define SM_SQ  (SM_REACH+1024)
#define SM_INV (SM_SQ+512)
#define SM_TS  (SM_INV+512)
#define SM_LAB (SM_TS+512)
#define SM_CAM (SM_LAB+512)
#define SM_B   (SM_CAM+512)
#define SMEM_TOTAL (SM_B+512)           // 102400

#define SW2(row, ch) ((row)*128 + ((((ch) ^ ((row)&7)))<<4))

// ---------------- device scratch ----------------
__device__ __nv_bfloat16 g_Fb[(size_t)Bn*Dn];
__device__ __nv_bfloat16 g_Wb[(size_t)CnP*Dn];
__device__ float    g_sq[Bn], g_invn[Bn];
__device__ float    g_sume[Bn], g_spos[Bn], g_cpos[Bn];
__device__ unsigned g_hp[Bn];
__device__ float    g_sume_cls[Bn], g_lab_logit[Bn];
__device__ float    g_acc[8];
__device__ unsigned g_done = 0;

__device__ __forceinline__ unsigned f2o(float f){
    unsigned u = __float_as_uint(f);
    return (u & 0x80000000u) ? ~u : (u | 0x80000000u);
}
__device__ __forceinline__ float o2f(unsigned u){
    return __uint_as_float((u & 0x80000000u) ? (u & 0x7fffffffu) : ~u);
}
__device__ __forceinline__ uint32_t pack_bf(float a, float b){
    __nv_bfloat162 t = __floats2bfloat162_rn(a, b);
    return *reinterpret_cast<uint32_t*>(&t);
}
__device__ __forceinline__ float sq2(uint32_t u){
    __nv_bfloat162 h = *reinterpret_cast<__nv_bfloat162*>(&u);
    float2 f = __bfloat1622float2(h);
    return f.x*f.x + f.y*f.y;
}

#define CP16(dst, src) asm volatile("cp.async.cg.shared.global [%0], [%1], 16;" :: "r"(dst), "l"(src) : "memory")
#define CP_COMMIT()    asm volatile("cp.async.commit_group;" ::: "memory")
#define CP_WAIT(n)     asm volatile("cp.async.wait_group %0;" :: "n"(n) : "memory")

__device__ __forceinline__ void ldm4(uint32_t &r0, uint32_t &r1, uint32_t &r2, uint32_t &r3, uint32_t addr){
    asm volatile("ldmatrix.sync.aligned.m8n8.x4.shared.b16 {%0,%1,%2,%3}, [%4];"
        : "=r"(r0), "=r"(r1), "=r"(r2), "=r"(r3) : "r"(addr));
}
__device__ __forceinline__ void mma16816(float* d, const uint32_t* a, const uint32_t* b){
    asm volatile("mma.sync.aligned.m16n8k16.row.col.f32.bf16.bf16.f32 "
        "{%0,%1,%2,%3}, {%4,%5,%6,%7}, {%8,%9}, {%0,%1,%2,%3};"
        : "+f"(d[0]), "+f"(d[1]), "+f"(d[2]), "+f"(d[3])
        : "r"(a[0]), "r"(a[1]), "r"(a[2]), "r"(a[3]), "r"(b[0]), "r"(b[1]));
}

// ---------------- convert F+W, norms+init fused; 2 F-rows per block, MLP=4 ----------------
__global__ void convert_kernel(const float* __restrict__ F, const float* __restrict__ W){
    __shared__ float s_part[2][4];
    int b = blockIdx.x, tid = threadIdx.x;
    if (b < Bn/2){
        int half = tid >> 7;                 // warps 0-3 -> row 2b, warps 4-7 -> row 2b+1
        int row  = b*2 + half;
        int lt   = tid & 127;
        size_t base = (size_t)row*Dn + (size_t)lt*16;
        float4 v0 = *(const float4*)(F+base);
        float4 v1 = *(const float4*)(F+base+4);
        float4 v2 = *(const float4*)(F+base+8);
        float4 v3 = *(const float4*)(F+base+12);
        uint4 o0, o1;
        o0.x = pack_bf(v0.x, v0.y); o0.y = pack_bf(v0.z, v0.w);
        o0.z = pack_bf(v1.x, v1.y); o0.w = pack_bf(v1.z, v1.w);
        o1.x = pack_bf(v2.x, v2.y); o1.y = pack_bf(v2.z, v2.w);
        o1.z = pack_bf(v3.x, v3.y); o1.w = pack_bf(v3.z, v3.w);
        *(uint4*)(g_Fb + base)     = o0;
        *(uint4*)(g_Fb + base + 8) = o1;
        float s = sq2(o0.x)+sq2(o0.y)+sq2(o0.z)+sq2(o0.w)
                + sq2(o1.x)+sq2(o1.y)+sq2(o1.z)+sq2(o1.w);
        #pragma unroll
        for (int of=16;of;of>>=1) s += __shfl_xor_sync(0xffffffffu, s, of);
        if ((tid&31)==0) s_part[half][(tid>>5)&3] = s;
        __syncthreads();
        if (lt == 0){
            float t = s_part[half][0]+s_part[half][1]+s_part[half][2]+s_part[half][3];
            g_sq[row]=t; g_invn[row]=rsqrtf(t);
            g_sume[row]=0.f; g_spos[row]=0.f; g_cpos[row]=0.f;
            g_hp[row]=f2o(-BIGF);
            g_sume_cls[row]=0.f; g_lab_logit[row]=0.f;
            if (row<8) g_acc[row]=0.f;
        }
    } else {
        size_t i = ((size_t)(b-Bn/2)*256 + tid)*8;
        size_t row = i / Dn;
        uint4 o;
        if (row < Cn){
            float4 v0 = *(const float4*)(W+i);
            float4 v1 = *(const float4*)(W+i+4);
            o.x = pack_bf(v0.x, v0.y); o.y = pack_bf(v0.z, v0.w);
            o.z = pack_bf(v1.x, v1.y); o.w = pack_bf(v1.z, v1.w);
        } else { o.x=o.y=o.z=o.w=0u; }
        *(uint4*)(g_Wb + i) = o;
    }
}

// ---------------- mega kernel: 2080 pair tiles + 384 cls tiles, 128x128, 2 CTA/SM ----------------
__global__ __launch_bounds__(256,2) void mega_kernel(
    const int* __restrict__ lab, const int* __restrict__ cam,
    const float* __restrict__ ts, const float* __restrict__ reach,
    const float* __restrict__ bbias)
{
    extern __shared__ char smem[];
    uint32_t sb = (uint32_t)__cvta_generic_to_shared(smem);
    int tid = threadIdx.x, lane = tid&31, wid = tid>>5;
    int wm = wid&3, wn = wid>>2;

    int t = blockIdx.x;
    bool isCls = (t >= NTILE_PAIR);
    bool diag = false;
    int row0, col0;
    const __nv_bfloat16* gBbase;
    if (isCls){
        int c = t - NTILE_PAIR;
        row0 = (c/6)*BM; col0 = (c%6)*BM;
        gBbase = g_Wb;
    } else {
        int I = (int)((129.0 - sqrt(16641.0 - 8.0*(double)t))*0.5);
        if (I < 0) I = 0; if (I > 63) I = 63;
        while (I < 63 && ((I+1)*(129-(I+1)))/2 <= t) I++;
        while (((I)*(129-I))/2 > t) I--;
        int J = I + (t - (I*(129-I))/2);
        diag = (I == J);
        row0 = I*BM; col0 = J*BM;
        gBbase = g_Fb;
    }

    float* s_reach=(float*)(smem+SM_REACH);
    float* s_sq  =(float*)(smem+SM_SQ);
    float* s_invn=(float*)(smem+SM_INV);
    float* s_ts  =(float*)(smem+SM_TS);
    int*   s_lab =(int*)  (smem+SM_LAB);
    int*   s_cam =(int*)  (smem+SM_CAM);
    float* s_b   =(float*)(smem+SM_B);
    if (!isCls){
        s_reach[tid] = reach[tid];
        if (tid < 128){
            int cj = col0 + tid;
            s_sq[tid]=g_sq[cj]; s_invn[tid]=g_invn[cj]; s_ts[tid]=ts[cj];
            s_lab[tid]=lab[cj]; s_cam[tid]=cam[cj];
        }
    } else if (tid < 128){
        int cj = col0 + tid;
        s_b[tid] = (cj < Cn) ? bbias[cj] : 0.f;
    }

    // loaders: 4 chunks of A + 4 of B per thread per stage
    int rL = tid>>3, cL = tid&7;
    uint32_t dA = SW2(rL, cL);
    const __nv_bfloat16* gA = g_Fb + (size_t)(row0+rL)*Dn + cL*8;
    const __nv_bfloat16* gB = gBbase + (size_t)(col0+rL)*Dn + cL*8;

    int q = lane>>3, rr = lane&7;
    int rowA[2], rowB[4];
    #pragma unroll
    for (int mt=0; mt<2; mt++) rowA[mt] = (wm*32 + mt*16 + rr + (q&1)*8)*128;
    #pragma unroll
    for (int nt4=0; nt4<4; nt4++) rowB[nt4] = 16384 + (wn*64 + nt4*16 + rr + (q>>1)*8)*128;
    int qhi = q>>1, qlo = q&1;

    float acc[2][8][4];
    #pragma unroll
    for (int i=0;i<2;i++)
        #pragma unroll
        for (int j=0;j<8;j++)
            #pragma unroll
            for (int e=0;e<4;e++) acc[i][j][e]=0.f;

    #define PLOAD(j, stq) do { \
        uint32_t _st = sb + (stq)*STG; \
        size_t _ko = (size_t)(j)*BK; \
        _Pragma("unroll") \
        for (int _i=0;_i<4;_i++){ \
            CP16(_st+dA+4096*_i,       gA + (size_t)(32*_i)*Dn + _ko); \
            CP16(_st+16384+dA+4096*_i, gB + (size_t)(32*_i)*Dn + _ko); \
        } \
    } while(0)

    PLOAD(0,0); CP_COMMIT();
    PLOAD(1,1); CP_COMMIT();

    int cs = 0, ls = 2;
    for (int j=0; j<KT; j++){
        CP_WAIT(1);
        __syncthreads();
        if (j+2 < KT){
            PLOAD(j+2, ls);
            ls++; if (ls==NST) ls=0;
        }
        CP_COMMIT();
        uint32_t st = sb + cs*STG;
        cs++; if (cs==NST) cs=0;
        #pragma unroll
        for (int ks=0; ks<4; ks++){
            uint32_t chA = st + ((((ks*2+qhi) ^ rr))<<4);
            uint32_t chB = st + ((((ks*2+qlo) ^ rr))<<4);
            uint32_t a[2][4], b[8][2];
            ldm4(a[0][0],a[0][1],a[0][2],a[0][3], chA + rowA[0]);
            ldm4(a[1][0],a[1][1],a[1][2],a[1][3], chA + rowA[1]);
            #pragma unroll
            for (int nt4=0; nt4<4; nt4++)
                ldm4(b[nt4*2][0],b[nt4*2][1],b[nt4*2+1][0],b[nt4*2+1][1], chB + rowB[nt4]);
            #pragma unroll
            for (int mt=0; mt<2; mt++)
                #pragma unroll
                for (int nt=0; nt<8; nt++)
                    mma16816(acc[mt][nt], a[mt], b[nt]);
        }
    }
    #undef PLOAD

    if (isCls){
        // ---- classifier epilogue ----
        float se4[4]; int r4c[4], labc[4];
        #pragma unroll
        for (int x=0;x<4;x++){
            int ri = row0 + wm*32 + (x>>1)*16 + (x&1)*8 + (lane>>2);
            r4c[x]=ri; labc[x]=lab[ri]; se4[x]=0.f;
        }
        #pragma unroll
        for (int nt=0; nt<8; nt++)
            #pragma unroll
            for (int u=0; u<2; u++){
                int cl = wn*64 + nt*8 + (lane&3)*2 + u;
                int cj = col0 + cl;
                if (cj < Cn){
                    float bj = s_b[cl];
                    #pragma unroll
                    for (int x=0;x<4;x++){
                        float logit = acc[x>>1][nt][(x&1)*2+u] + bj;
                        se4[x] += __expf(logit);
                        if (cj == labc[x]) g_lab_logit[r4c[x]] = logit;
                    }
                }
            }
        #pragma unroll
        for (int o=1;o<=2;o<<=1)
            #pragma unroll
            for (int x=0;x<4;x++)
                se4[x] += __shfl_xor_sync(0xffffffffu, se4[x], o);
        if ((lane&3)==0){
            #pragma unroll
            for (int x=0;x<4;x++) atomicAdd(&g_sume_cls[r4c[x]], se4[x]);
        }
        return;
    }

    // ---- dual-side pair epilogue (hardest_neg == 0 identically; not tracked) ----
    int   r4[4], labi[4], cami[4];
    float sqi[4], ari[4], tsi[4];
    #pragma unroll
    for (int x=0;x<4;x++){
        int ri = row0 + wm*32 + (x>>1)*16 + (x&1)*8 + (lane>>2);
        r4[x]=ri; sqi[x]=g_sq[ri]; ari[x]=g_invn[ri]*CEXP;
        tsi[x]=ts[ri]; labi[x]=lab[ri]; cami[x]=cam[ri];
    }
    float sume4[4], spos4[4], cpos4[4], hp4[4];
    #pragma unroll
    for (int x=0;x<4;x++){ sume4[x]=0.f; spos4[x]=0.f; cpos4[x]=0.f; hp4[x]=-BIGF; }

    #pragma unroll
    for (int nt=0; nt<8; nt++){
        #pragma unroll
        for (int u=0; u<2; u++){
            int cl = wn*64 + nt*8 + (lane&3)*2 + u;
            int cj = col0 + cl;
            float sqj=s_sq[cl], invj=s_invn[cl], tsj=s_ts[cl];
            int labj=s_lab[cl], camj=s_cam[cl];
            float hpC=-BIGF, sumeC=0.f, sposC=0.f, cposC=0.f;
            #pragma unroll
            for (int mt=0; mt<2; mt++){
                #pragma unroll
                for (int h=0; h<2; h++){
                    int x = mt*2 + h;
                    float g  = acc[mt][nt][h*2+u];
                    bool eye  = (r4[x] == cj);
                    bool sne  = (labi[x] == labj) && !eye;
                    float tt = fmaf(g*ari[x], invj, -CEXP);
                    float ev; asm("ex2.approx.ftz.f32 %0, %1;" : "=f"(ev) : "f"(tt));
                    float dt = fabsf(tsi[x] - tsj);
                    sume4[x] += ev;
                    if (sne){
                        float d2 = fmaxf(fmaf(-2.f, g, sqi[x] + sqj), 0.f);
                        hp4[x] = fmaxf(hp4[x], d2);
                        if (dt <= s_reach[cami[x]*NCAMS + camj]){
                            spos4[x] += fmaf(tt, LN2f, IT); cpos4[x] += 1.f;
                        }
                        if (!diag){
                            hpC = fmaxf(hpC, d2);
                            if (dt <= s_reach[camj*NCAMS + cami[x]]){
                                sposC += fmaf(tt, LN2f, IT); cposC += 1.f;
                            }
                        }
                    }
                    if (!diag) sumeC += ev;
                }
            }
            if (!diag){
                #pragma unroll
                for (int o=4; o<=16; o<<=1){
                    sumeC += __shfl_xor_sync(0xffffffffu, sumeC, o);
                    sposC += __shfl_xor_sync(0xffffffffu, sposC, o);
                    cposC += __shfl_xor_sync(0xffffffffu, cposC, o);
                    hpC = fmaxf(hpC, __shfl_xor_sync(0xffffffffu, hpC, o));
                }
                if ((lane>>2) == 0){
                    atomicAdd(&g_sume[cj], sumeC);
                    if (cposC > 0.f){ atomicAdd(&g_spos[cj], sposC); atomicAdd(&g_cpos[cj], cposC); }
                    if (hpC > -BIGF) atomicMax(&g_hp[cj], f2o(hpC));
                }
            }
        }
    }

    // row-side merge
    #pragma unroll
    for (int o=1; o<=2; o<<=1){
        #pragma unroll
        for (int x=0;x<4;x++){
            sume4[x] += __shfl_xor_sync(0xffffffffu, sume4[x], o);
            spos4[x] += __shfl_xor_sync(0xffffffffu, spos4[x], o);
            cpos4[x] += __shfl_xor_sync(0xffffffffu, cpos4[x], o);
            hp4[x] = fmaxf(hp4[x], __shfl_xor_sync(0xffffffffu, hp4[x], o));
        }
    }
    if ((lane&3)==0){
        #pragma unroll
        for (int x=0;x<4;x++){
            int ri = r4[x];
            atomicAdd(&g_sume[ri], sume4[x]);
            if (cpos4[x] > 0.f){ atomicAdd(&g_spos[ri], spos4[x]); atomicAdd(&g_cpos[ri], cpos4[x]); }
            if (hp4[x] > -BIGF) atomicMax(&g_hp[ri], f2o(hp4[x]));
        }
    }
}

// ---------------- finalization (single kernel, last-block pattern) ----------------
__global__ void fin1(float* out){
    int i = blockIdx.x*blockDim.x + threadIdx.x;
    float tri=0.f, nv=0.f, stn=0.f, stc=0.f, cls=0.f;
    if (i < Bn){
        float lse = IT + logf(g_sume[i]);
        stn = g_spos[i] - g_cpos[i]*lse;
        stc = g_cpos[i];
        float hp = o2f(g_hp[i]);
        bool valid = hp > -1.0e8f;
        tri = valid ? fmaxf(hp + MARGINF, 0.f) : 0.f;   // hardest_neg == 0 identically
        nv  = valid ? 1.f : 0.f;
        cls = logf(g_sume_cls[i]) - g_lab_logit[i];
    }
    #pragma unroll
    for (int o=16;o;o>>=1){
        tri += __shfl_down_sync(0xffffffffu, tri, o);
        nv  += __shfl_down_sync(0xffffffffu, nv , o);
        stn += __shfl_down_sync(0xffffffffu, stn, o);
        stc += __shfl_down_sync(0xffffffffu, stc, o);
        cls += __shfl_down_sync(0xffffffffu, cls, o);
    }
    if ((threadIdx.x & 31) == 0){
        atomicAdd(&g_acc[0], tri);
        atomicAdd(&g_acc[1], nv);
        atomicAdd(&g_acc[2], stn);
        atomicAdd(&g_acc[3], stc);
        atomicAdd(&g_acc[4], cls);
    }
    __syncthreads();
    __threadfence();
    if (threadIdx.x == 0){
        unsigned prev = atomicAdd(&g_done, 1u);
        if (prev == (unsigned)(gridDim.x - 1)){
            float nvv = g_acc[1], npos = g_acc[3];
            float loss_id  = g_acc[4] / (float)Bn;
            float loss_tri = (nvv  > 0.f) ? g_acc[0] / fmaxf(nvv,  1.f) : 0.f;
            float loss_st  = (npos > 0.f) ? (-g_acc[2]) / fmaxf(npos, 1.f) : 0.f;
            out[0] = loss_id + L_TRI*loss_tri + L_ST*loss_st;
            g_done = 0;   // reset for graph replay
        }
    }
}

// ---------------- launch ----------------
extern "C" void kernel_launch(void* const* d_in, const int* in_sizes, int n_in,
                              void* d_out, int out_size){
    const float* F     = (const float*)d_in[0];
    const int*   lab   = (const int*)  d_in[1];
    const int*   cam   = (const int*)  d_in[2];
    const float* ts    = (const float*)d_in[3];
    const float* reach = (const float*)d_in[4];
    const float* W     = (const float*)d_in[5];
    const float* bbias = (const float*)d_in[6];
    float* out = (float*)d_out;

    cudaFuncSetAttribute(mega_kernel, cudaFuncAttributeMaxDynamicSharedMemorySize, SMEM_TOTAL);

    convert_kernel<<<Bn/2 + CnP, 256>>>(F, W);
    mega_kernel<<<NTILE_ALL, 256, SMEM_TOTAL>>>(lab, cam, ts, reach, bbias);
    fin1<<<Bn/256, 256>>>(out);
}